// round 1
// baseline (speedup 1.0000x reference)
#include <cuda_runtime.h>
#include <math.h>

#define BATCH 8
#define TLEN  4096
#define DDIM  512
#define HDIM  1024
#define MROWS (BATCH*TLEN)   // 32768

// ---------------- scratch (device globals, no allocation) ----------------
__device__ float g_x1[MROWS*DDIM];        // 64MB
__device__ float g_qsig[MROWS*HDIM];      // 128MB
__device__ float g_numer[MROWS*HDIM];     // 128MB
__device__ float g_v[MROWS*HDIM];         // 128MB
__device__ float g_weighted[TLEN*HDIM];   // 16MB
__device__ float g_x2[MROWS*DDIM];        // 64MB
__device__ float g_x3[MROWS*DDIM];        // 64MB
__device__ float g_h[MROWS*HDIM];         // 128MB

// ---------------- LayerNorm: one block per row, D=512 ----------------
__global__ __launch_bounds__(128) void ln_kernel(
    const float* __restrict__ x, const float* __restrict__ gamma,
    const float* __restrict__ beta, float* __restrict__ out)
{
    const int row = blockIdx.x;
    const int t   = threadIdx.x;             // 128 threads * float4 = 512
    const float4* xr = (const float4*)(x + (size_t)row * DDIM);
    float4 v = xr[t];
    float s  = v.x + v.y + v.z + v.w;
    float ss = v.x*v.x + v.y*v.y + v.z*v.z + v.w*v.w;

    __shared__ float red[2][4];
    const int lane = t & 31, wid = t >> 5;
    #pragma unroll
    for (int o = 16; o > 0; o >>= 1) {
        s  += __shfl_xor_sync(0xffffffffu, s,  o);
        ss += __shfl_xor_sync(0xffffffffu, ss, o);
    }
    if (lane == 0) { red[0][wid] = s; red[1][wid] = ss; }
    __syncthreads();
    s  = red[0][0] + red[0][1] + red[0][2] + red[0][3];
    ss = red[1][0] + red[1][1] + red[1][2] + red[1][3];

    const float mean = s * (1.0f / DDIM);
    const float var  = ss * (1.0f / DDIM) - mean * mean;
    const float rstd = rsqrtf(var + 1e-5f);

    const float4 g4 = ((const float4*)gamma)[t];
    const float4 b4 = ((const float4*)beta)[t];
    float4 o4;
    o4.x = (v.x - mean) * rstd * g4.x + b4.x;
    o4.y = (v.y - mean) * rstd * g4.y + b4.y;
    o4.z = (v.z - mean) * rstd * g4.z + b4.z;
    o4.w = (v.w - mean) * rstd * g4.w + b4.w;
    ((float4*)(out + (size_t)row * DDIM))[t] = o4;
}

// ---------------- AFT batch reduction: weighted[t,h] ----------------
__global__ __launch_bounds__(256) void aft_reduce_kernel(
    const float* __restrict__ numer, const float* __restrict__ v,
    float* __restrict__ weighted)
{
    const int i = blockIdx.x * blockDim.x + threadIdx.x;  // 0..T*H-1
    float den = 0.f, num = 0.f;
    #pragma unroll
    for (int b = 0; b < BATCH; ++b) {
        const size_t idx = (size_t)b * (TLEN * HDIM) + i;
        const float n  = numer[idx];
        const float vv = v[idx];
        den += n;
        num = fmaf(n, vv, num);
    }
    weighted[i] = num / den;
}

// ---------------- GEMM: C[M,N] = op(A)[M,K] * B[K,N], fused epilogues -----
// EPI: 0 plain(+bias) | 1 sigmoid | 2 exp(+bias+bias2) | 3 +bias+resid
//      4 gelu | 5 2*(+bias)
// AMUL: A[m,k] *= wmul[(m % TLEN)*K + k]
template<int EPI, bool AMUL>
__global__ __launch_bounds__(256) void gemm_kernel(
    const float* __restrict__ A, const float* __restrict__ Bm,
    const float* __restrict__ bias, const float* __restrict__ bias2,
    const float* __restrict__ wmul, const float* __restrict__ resid,
    float* __restrict__ C, int M, int N, int K)
{
    __shared__ float As[16][128];
    __shared__ float Bs[16][128];

    const int tid = threadIdx.x;
    const int bm = blockIdx.y * 128;
    const int bn = blockIdx.x * 128;
    const int tx = tid & 15, ty = tid >> 4;
    const int m0 = ty * 8, n0 = tx * 8;

    float acc[8][8];
    #pragma unroll
    for (int i = 0; i < 8; ++i)
        #pragma unroll
        for (int j = 0; j < 8; ++j) acc[i][j] = 0.f;

    for (int k0 = 0; k0 < K; k0 += 16) {
        // load A tile (128 rows x 16 k) and B tile (16 k x 128 cols)
        #pragma unroll
        for (int it = 0; it < 2; ++it) {
            const int idx = tid + it * 256;           // 0..511
            // A: row = idx/4, k-quad = idx%4
            const int ar = idx >> 2;
            const int ak = (idx & 3) * 4;
            float4 a4 = *(const float4*)(A + (size_t)(bm + ar) * K + k0 + ak);
            if (AMUL) {
                const int tt = (bm + ar) & (TLEN - 1);
                const float4 w4 = *(const float4*)(wmul + (size_t)tt * K + k0 + ak);
                a4.x *= w4.x; a4.y *= w4.y; a4.z *= w4.z; a4.w *= w4.w;
            }
            As[ak + 0][ar] = a4.x;
            As[ak + 1][ar] = a4.y;
            As[ak + 2][ar] = a4.z;
            As[ak + 3][ar] = a4.w;
            // B: row = idx/32, col-quad = idx%32
            const int br = idx >> 5;
            const int bc = (idx & 31) * 4;
            *(float4*)&Bs[br][bc] =
                *(const float4*)(Bm + (size_t)(k0 + br) * N + bn + bc);
        }
        __syncthreads();

        #pragma unroll
        for (int kk = 0; kk < 16; ++kk) {
            const float4 a0 = *(const float4*)&As[kk][m0];
            const float4 a1 = *(const float4*)&As[kk][m0 + 4];
            const float4 b0 = *(const float4*)&Bs[kk][n0];
            const float4 b1 = *(const float4*)&Bs[kk][n0 + 4];
            const float ar[8] = {a0.x, a0.y, a0.z, a0.w, a1.x, a1.y, a1.z, a1.w};
            const float br[8] = {b0.x, b0.y, b0.z, b0.w, b1.x, b1.y, b1.z, b1.w};
            #pragma unroll
            for (int i = 0; i < 8; ++i)
                #pragma unroll
                for (int j = 0; j < 8; ++j)
                    acc[i][j] = fmaf(ar[i], br[j], acc[i][j]);
        }
        __syncthreads();
    }

    // epilogue
    #pragma unroll
    for (int i = 0; i < 8; ++i) {
        const int m = bm + m0 + i;
        float* crow = C + (size_t)m * N + bn + n0;
        const float* rrow = (EPI == 3) ? (resid + (size_t)m * N + bn + n0) : nullptr;
        #pragma unroll
        for (int j = 0; j < 8; j += 4) {
            float4 o;
            float vals[4];
            #pragma unroll
            for (int e = 0; e < 4; ++e) {
                const int n = bn + n0 + j + e;
                float v = acc[i][j + e] + bias[n];
                if (EPI == 1) {
                    v = 1.0f / (1.0f + expf(-v));
                } else if (EPI == 2) {
                    v = expf(v + bias2[n]);
                } else if (EPI == 3) {
                    v = v + rrow[j + e];
                } else if (EPI == 4) {
                    v = 0.5f * v * (1.0f + erff(v * 0.70710678118654752f));
                } else if (EPI == 5) {
                    v = 2.0f * v;
                }
                vals[e] = v;
            }
            o.x = vals[0]; o.y = vals[1]; o.z = vals[2]; o.w = vals[3];
            *(float4*)(crow + j) = o;
        }
    }
}

// ---------------- launch ----------------
extern "C" void kernel_launch(void* const* d_in, const int* in_sizes, int n_in,
                              void* d_out, int out_size)
{
    const float* x     = (const float*)d_in[0];
    const float* gamma = (const float*)d_in[1];
    const float* beta  = (const float*)d_in[2];
    const float* Wq    = (const float*)d_in[3];
    const float* bq    = (const float*)d_in[4];
    const float* Wk    = (const float*)d_in[5];
    const float* bk    = (const float*)d_in[6];
    const float* Wv    = (const float*)d_in[7];
    const float* bv    = (const float*)d_in[8];
    const float* wbias = (const float*)d_in[9];
    const float* Wo    = (const float*)d_in[10];
    const float* bo    = (const float*)d_in[11];
    const float* W1    = (const float*)d_in[12];
    const float* b1    = (const float*)d_in[13];
    const float* W2    = (const float*)d_in[14];
    const float* b2    = (const float*)d_in[15];
    float* out = (float*)d_out;

    float *x1, *qsig, *numer, *vmat, *weighted, *x2, *x3, *hbuf;
    cudaGetSymbolAddress((void**)&x1,       g_x1);
    cudaGetSymbolAddress((void**)&qsig,     g_qsig);
    cudaGetSymbolAddress((void**)&numer,    g_numer);
    cudaGetSymbolAddress((void**)&vmat,     g_v);
    cudaGetSymbolAddress((void**)&weighted, g_weighted);
    cudaGetSymbolAddress((void**)&x2,       g_x2);
    cudaGetSymbolAddress((void**)&x3,       g_x3);
    cudaGetSymbolAddress((void**)&hbuf,     g_h);

    // 1) x1 = LN(x)
    ln_kernel<<<MROWS, 128>>>(x, gamma, beta, x1);

    // 2-4) Q/K/V GEMMs with fused epilogues
    dim3 gQ(HDIM / 128, MROWS / 128);
    gemm_kernel<1, false><<<gQ, 256>>>(x1, Wq, bq, nullptr, nullptr, nullptr,
                                       qsig, MROWS, HDIM, DDIM);
    gemm_kernel<2, false><<<gQ, 256>>>(x1, Wk, bk, wbias, nullptr, nullptr,
                                       numer, MROWS, HDIM, DDIM);
    gemm_kernel<0, false><<<gQ, 256>>>(x1, Wv, bv, nullptr, nullptr, nullptr,
                                       vmat, MROWS, HDIM, DDIM);

    // 5) weighted[t,h] = sum_b numer*V / sum_b numer
    aft_reduce_kernel<<<(TLEN * HDIM) / 256, 256>>>(numer, vmat, weighted);

    // 6) x2 = (Qsig .* weighted) @ Wo + bo + x1
    dim3 gO(DDIM / 128, MROWS / 128);
    gemm_kernel<3, true><<<gO, 256>>>(qsig, Wo, bo, nullptr, weighted, x1,
                                      x2, MROWS, DDIM, HDIM);

    // 7) x3 = LN(x2)
    ln_kernel<<<MROWS, 128>>>(x2, gamma, beta, x3);

    // 8) h = gelu(x3 @ W1 + b1)
    gemm_kernel<4, false><<<gQ, 256>>>(x3, W1, b1, nullptr, nullptr, nullptr,
                                       hbuf, MROWS, HDIM, DDIM);

    // 9) out = 2*(h @ W2 + b2)
    gemm_kernel<5, false><<<gO, 256>>>(hbuf, W2, b2, nullptr, nullptr, nullptr,
                                       out, MROWS, DDIM, HDIM);
}

// round 3
// speedup vs baseline: 1.0654x; 1.0654x over previous
#include <cuda_runtime.h>
#include <cuda_bf16.h>
#include <math.h>
#include <stdint.h>

#define BATCH 8
#define TLEN  4096
#define DDIM  512
#define HDIM  1024
#define MROWS (BATCH*TLEN)   // 32768

// ---------------- scratch (device globals, no allocation) ----------------
__device__ float g_x1[MROWS*DDIM];
__device__ float g_qsig[MROWS*HDIM];
__device__ float g_numer[MROWS*HDIM];
__device__ float g_v[MROWS*HDIM];
__device__ float g_weighted[TLEN*HDIM];
__device__ float g_x2[MROWS*DDIM];
__device__ float g_x3[MROWS*DDIM];
__device__ float g_h[MROWS*HDIM];

// ================= helpers =================
__device__ __forceinline__ uint32_t smem_u32(const void* p) {
    uint32_t a;
    asm("{ .reg .u64 t; cvta.to.shared.u64 t, %1; cvt.u32.u64 %0, t; }"
        : "=r"(a) : "l"(p));
    return a;
}
__device__ __forceinline__ uint32_t swz128(uint32_t off) {
    return off ^ ((off >> 3) & 0x70);
}
// split a pair of fp32 into packed bf16 hi and lo (residual)
__device__ __forceinline__ void split2(float a, float b, uint32_t& hi, uint32_t& lo) {
    __nv_bfloat16 ha = __float2bfloat16_rn(a);
    __nv_bfloat16 hb = __float2bfloat16_rn(b);
    float ra = a - __bfloat162float(ha);
    float rb = b - __bfloat162float(hb);
    __nv_bfloat16 la = __float2bfloat16_rn(ra);
    __nv_bfloat16 lb = __float2bfloat16_rn(rb);
    hi = (uint32_t)__bfloat16_as_ushort(ha) | ((uint32_t)__bfloat16_as_ushort(hb) << 16);
    lo = (uint32_t)__bfloat16_as_ushort(la) | ((uint32_t)__bfloat16_as_ushort(lb) << 16);
}
__device__ __forceinline__ void ldsm_x4(uint32_t& r0, uint32_t& r1,
                                        uint32_t& r2, uint32_t& r3, uint32_t addr) {
    asm volatile("ldmatrix.sync.aligned.m8n8.x4.shared.b16 {%0,%1,%2,%3}, [%4];"
                 : "=r"(r0), "=r"(r1), "=r"(r2), "=r"(r3) : "r"(addr));
}
__device__ __forceinline__ void mma_bf16(float* d, const uint32_t* a,
                                         uint32_t b0, uint32_t b1) {
    asm volatile("mma.sync.aligned.m16n8k16.row.col.f32.bf16.bf16.f32 "
                 "{%0,%1,%2,%3}, {%4,%5,%6,%7}, {%8,%9}, {%0,%1,%2,%3};"
                 : "+f"(d[0]), "+f"(d[1]), "+f"(d[2]), "+f"(d[3])
                 : "r"(a[0]), "r"(a[1]), "r"(a[2]), "r"(a[3]), "r"(b0), "r"(b1));
}

// ---------------- LayerNorm ----------------
__global__ __launch_bounds__(128) void ln_kernel(
    const float* __restrict__ x, const float* __restrict__ gamma,
    const float* __restrict__ beta, float* __restrict__ out)
{
    const int row = blockIdx.x;
    const int t   = threadIdx.x;
    const float4* xr = (const float4*)(x + (size_t)row * DDIM);
    float4 v = xr[t];
    float s  = v.x + v.y + v.z + v.w;
    float ss = v.x*v.x + v.y*v.y + v.z*v.z + v.w*v.w;

    __shared__ float red[2][4];
    const int lane = t & 31, wid = t >> 5;
    #pragma unroll
    for (int o = 16; o > 0; o >>= 1) {
        s  += __shfl_xor_sync(0xffffffffu, s,  o);
        ss += __shfl_xor_sync(0xffffffffu, ss, o);
    }
    if (lane == 0) { red[0][wid] = s; red[1][wid] = ss; }
    __syncthreads();
    s  = red[0][0] + red[0][1] + red[0][2] + red[0][3];
    ss = red[1][0] + red[1][1] + red[1][2] + red[1][3];

    const float mean = s * (1.0f / DDIM);
    const float var  = ss * (1.0f / DDIM) - mean * mean;
    const float rstd = rsqrtf(var + 1e-5f);

    const float4 g4 = ((const float4*)gamma)[t];
    const float4 b4 = ((const float4*)beta)[t];
    float4 o4;
    o4.x = (v.x - mean) * rstd * g4.x + b4.x;
    o4.y = (v.y - mean) * rstd * g4.y + b4.y;
    o4.z = (v.z - mean) * rstd * g4.z + b4.z;
    o4.w = (v.w - mean) * rstd * g4.w + b4.w;
    ((float4*)(out + (size_t)row * DDIM))[t] = o4;
}

// ---------------- AFT batch reduction ----------------
__global__ __launch_bounds__(256) void aft_reduce_kernel(
    const float* __restrict__ numer, const float* __restrict__ v,
    float* __restrict__ weighted)
{
    const int i = blockIdx.x * blockDim.x + threadIdx.x;
    float den = 0.f, num = 0.f;
    #pragma unroll
    for (int b = 0; b < BATCH; ++b) {
        const size_t idx = (size_t)b * (TLEN * HDIM) + i;
        const float n  = numer[idx];
        const float vv = v[idx];
        den += n;
        num = fmaf(n, vv, num);
    }
    weighted[i] = num / den;
}

// ================= HMMA (mma.sync) GEMM, 3-pass bf16 split =================
// C[M,N] = op(A)[M,K] * B[K,N]
// EPI: 0 +bias | 1 sigmoid | 2 exp(+bias+bias2) | 3 +bias+resid | 4 gelu | 5 2*(+bias)
// AMUL: A[m,k] *= wmul[(m % TLEN)*K + k]
#define TM 128
#define TN 128
#define TK 64

#define SM_A_HI 0
#define SM_A_LO (SM_A_HI + TM*TK*2)       // +16KB
#define SM_B_HI (SM_A_LO + TM*TK*2)
#define SM_B_LO (SM_B_HI + TN*TK*2)
#define SMEM_BYTES (SM_B_LO + TN*TK*2)    // 65536

template<int EPI, bool AMUL>
__global__ __launch_bounds__(256, 2) void tc_gemm(
    const float* __restrict__ A, const float* __restrict__ Bm,
    const float* __restrict__ bias, const float* __restrict__ bias2,
    const float* __restrict__ wmul, const float* __restrict__ resid,
    float* __restrict__ C, int M, int N, int K)
{
    extern __shared__ char smem[];
    const uint32_t sb  = smem_u32(smem);
    const int tid  = threadIdx.x;
    const int wid  = tid >> 5;
    const int lane = tid & 31;
    const int bm = blockIdx.y * TM;
    const int bn = blockIdx.x * TN;

    // warp tile: 64 (m) x 32 (n)
    const int wm = (wid >> 2) * 64;
    const int wn = (wid & 3) * 32;

    // ldmatrix lane address components
    const int rowA = lane & 15;              // A: row within m16 tile
    const int khA  = lane >> 4;              // A: k half (0/1)
    const int rowB = (lane & 7) + ((lane >> 4) << 3);  // B: n within n16 pair
    const int khB  = (lane >> 3) & 1;        // B: k half

    float acc[4][4][4];
    #pragma unroll
    for (int mi = 0; mi < 4; ++mi)
        #pragma unroll
        for (int ni = 0; ni < 4; ++ni)
            #pragma unroll
            for (int r = 0; r < 4; ++r) acc[mi][ni][r] = 0.f;

    const int nchunks = K / TK;
    for (int c = 0; c < nchunks; ++c) {
        const int k0 = c * TK;

        // ---- load + split A tile: 128 rows x 64 k ----
        #pragma unroll
        for (int it = 0; it < 8; ++it) {
            const int idx = tid + it * 256;
            const int ar = idx >> 4;          // row 0..127
            const int ac = (idx & 15) << 2;   // k 0..60 step 4
            float4 a4 = *(const float4*)(A + (size_t)(bm + ar) * K + k0 + ac);
            if (AMUL) {
                const int tt = (bm + ar) & (TLEN - 1);
                const float4 w4 = *(const float4*)(wmul + (size_t)tt * K + k0 + ac);
                a4.x *= w4.x; a4.y *= w4.y; a4.z *= w4.z; a4.w *= w4.w;
            }
            uint32_t h01, l01, h23, l23;
            split2(a4.x, a4.y, h01, l01);
            split2(a4.z, a4.w, h23, l23);
            const uint32_t so = swz128((uint32_t)(ar * 128 + ac * 2));
            *(uint2*)(smem + SM_A_HI + so) = make_uint2(h01, h23);
            *(uint2*)(smem + SM_A_LO + so) = make_uint2(l01, l23);
        }
        // ---- load + split B tile (transpose to [n][k]): 64 k x 128 n ----
        #pragma unroll
        for (int it = 0; it < 4; ++it) {
            const int idx = tid + it * 256;
            const int kp = idx >> 5;          // k-pair 0..31
            const int nq = (idx & 31) << 2;   // n 0..124 step 4
            const float* bp = Bm + (size_t)(k0 + kp * 2) * N + bn + nq;
            float4 b0 = *(const float4*)bp;
            float4 b1 = *(const float4*)(bp + N);
            const float* f0 = &b0.x;
            const float* f1 = &b1.x;
            #pragma unroll
            for (int j = 0; j < 4; ++j) {
                uint32_t hi, lo;
                split2(f0[j], f1[j], hi, lo);
                const uint32_t so = swz128((uint32_t)((nq + j) * 128 + kp * 4));
                *(uint32_t*)(smem + SM_B_HI + so) = hi;
                *(uint32_t*)(smem + SM_B_LO + so) = lo;
            }
        }
        __syncthreads();

        // ---- 3 passes: AhiBhi, AloBhi, AhiBlo ----
        #pragma unroll
        for (int pass = 0; pass < 3; ++pass) {
            const uint32_t aBase = sb + ((pass == 1) ? SM_A_LO : SM_A_HI);
            const uint32_t bBase = sb + ((pass == 2) ? SM_B_LO : SM_B_HI);
            #pragma unroll
            for (int s = 0; s < 4; ++s) {
                uint32_t afr[4][4];
                #pragma unroll
                for (int mi = 0; mi < 4; ++mi) {
                    const uint32_t off = (uint32_t)((wm + mi * 16 + rowA) * 128
                                                    + s * 32 + khA * 16);
                    ldsm_x4(afr[mi][0], afr[mi][1], afr[mi][2], afr[mi][3],
                            aBase + swz128(off));
                }
                uint32_t bfr[2][4];
                #pragma unroll
                for (int nj = 0; nj < 2; ++nj) {
                    const uint32_t off = (uint32_t)((wn + nj * 16 + rowB) * 128
                                                    + s * 32 + khB * 16);
                    ldsm_x4(bfr[nj][0], bfr[nj][1], bfr[nj][2], bfr[nj][3],
                            bBase + swz128(off));
                }
                #pragma unroll
                for (int mi = 0; mi < 4; ++mi) {
                    #pragma unroll
                    for (int ni = 0; ni < 4; ++ni) {
                        const uint32_t* bb = bfr[ni >> 1];
                        mma_bf16(acc[mi][ni], afr[mi],
                                 bb[(ni & 1) * 2], bb[(ni & 1) * 2 + 1]);
                    }
                }
            }
        }
        __syncthreads();
    }

    // ---- epilogue ----
    const int qid = lane >> 2;        // 0..7
    const int tc  = (lane & 3) * 2;   // 0,2,4,6
    #pragma unroll
    for (int mi = 0; mi < 4; ++mi) {
        #pragma unroll
        for (int half = 0; half < 2; ++half) {
            const int m = bm + wm + mi * 16 + qid + half * 8;
            float* crow = C + (size_t)m * N;
            const float* rrow = (EPI == 3) ? (resid + (size_t)m * N) : nullptr;
            #pragma unroll
            for (int ni = 0; ni < 4; ++ni) {
                const int n = bn + wn + ni * 8 + tc;
                float v0 = acc[mi][ni][half * 2 + 0] + bias[n];
                float v1 = acc[mi][ni][half * 2 + 1] + bias[n + 1];
                if (EPI == 1) {
                    v0 = 1.0f / (1.0f + expf(-v0));
                    v1 = 1.0f / (1.0f + expf(-v1));
                } else if (EPI == 2) {
                    v0 = expf(v0 + bias2[n]);
                    v1 = expf(v1 + bias2[n + 1]);
                } else if (EPI == 3) {
                    v0 += rrow[n];
                    v1 += rrow[n + 1];
                } else if (EPI == 4) {
                    v0 = 0.5f * v0 * (1.0f + erff(v0 * 0.70710678118654752f));
                    v1 = 0.5f * v1 * (1.0f + erff(v1 * 0.70710678118654752f));
                } else if (EPI == 5) {
                    v0 *= 2.0f;
                    v1 *= 2.0f;
                }
                float2 o; o.x = v0; o.y = v1;
                *(float2*)(crow + n) = o;
            }
        }
    }
}

// ---------------- launch ----------------
extern "C" void kernel_launch(void* const* d_in, const int* in_sizes, int n_in,
                              void* d_out, int out_size)
{
    const float* x     = (const float*)d_in[0];
    const float* gamma = (const float*)d_in[1];
    const float* beta  = (const float*)d_in[2];
    const float* Wq    = (const float*)d_in[3];
    const float* bq    = (const float*)d_in[4];
    const float* Wk    = (const float*)d_in[5];
    const float* bk    = (const float*)d_in[6];
    const float* Wv    = (const float*)d_in[7];
    const float* bv    = (const float*)d_in[8];
    const float* wbias = (const float*)d_in[9];
    const float* Wo    = (const float*)d_in[10];
    const float* bo    = (const float*)d_in[11];
    const float* W1    = (const float*)d_in[12];
    const float* b1    = (const float*)d_in[13];
    const float* W2    = (const float*)d_in[14];
    const float* b2    = (const float*)d_in[15];
    float* out = (float*)d_out;

    float *x1, *qsig, *numer, *vmat, *weighted, *x2, *x3, *hbuf;
    cudaGetSymbolAddress((void**)&x1,       g_x1);
    cudaGetSymbolAddress((void**)&qsig,     g_qsig);
    cudaGetSymbolAddress((void**)&numer,    g_numer);
    cudaGetSymbolAddress((void**)&vmat,     g_v);
    cudaGetSymbolAddress((void**)&weighted, g_weighted);
    cudaGetSymbolAddress((void**)&x2,       g_x2);
    cudaGetSymbolAddress((void**)&x3,       g_x3);
    cudaGetSymbolAddress((void**)&hbuf,     g_h);

    cudaFuncSetAttribute(tc_gemm<1, false>, cudaFuncAttributeMaxDynamicSharedMemorySize, SMEM_BYTES);
    cudaFuncSetAttribute(tc_gemm<2, false>, cudaFuncAttributeMaxDynamicSharedMemorySize, SMEM_BYTES);
    cudaFuncSetAttribute(tc_gemm<0, false>, cudaFuncAttributeMaxDynamicSharedMemorySize, SMEM_BYTES);
    cudaFuncSetAttribute(tc_gemm<3, true >, cudaFuncAttributeMaxDynamicSharedMemorySize, SMEM_BYTES);
    cudaFuncSetAttribute(tc_gemm<4, false>, cudaFuncAttributeMaxDynamicSharedMemorySize, SMEM_BYTES);
    cudaFuncSetAttribute(tc_gemm<5, false>, cudaFuncAttributeMaxDynamicSharedMemorySize, SMEM_BYTES);

    // 1) x1 = LN(x)
    ln_kernel<<<MROWS, 128>>>(x, gamma, beta, x1);

    // 2-4) Q/K/V GEMMs (fused epilogues)
    dim3 gQ(HDIM / TN, MROWS / TM);
    tc_gemm<1, false><<<gQ, 256, SMEM_BYTES>>>(x1, Wq, bq, nullptr, nullptr, nullptr,
                                               qsig, MROWS, HDIM, DDIM);
    tc_gemm<2, false><<<gQ, 256, SMEM_BYTES>>>(x1, Wk, bk, wbias, nullptr, nullptr,
                                               numer, MROWS, HDIM, DDIM);
    tc_gemm<0, false><<<gQ, 256, SMEM_BYTES>>>(x1, Wv, bv, nullptr, nullptr, nullptr,
                                               vmat, MROWS, HDIM, DDIM);

    // 5) weighted[t,h] = sum_b numer*V / sum_b numer
    aft_reduce_kernel<<<(TLEN * HDIM) / 256, 256>>>(numer, vmat, weighted);

    // 6) x2 = (Qsig .* weighted) @ Wo + bo + x1
    dim3 gO(DDIM / TN, MROWS / TM);
    tc_gemm<3, true><<<gO, 256, SMEM_BYTES>>>(qsig, Wo, bo, nullptr, weighted, x1,
                                              x2, MROWS, DDIM, HDIM);

    // 7) x3 = LN(x2)
    ln_kernel<<<MROWS, 128>>>(x2, gamma, beta, x3);

    // 8) h = gelu(x3 @ W1 + b1)
    tc_gemm<4, false><<<gQ, 256, SMEM_BYTES>>>(x3, W1, b1, nullptr, nullptr, nullptr,
                                               hbuf, MROWS, HDIM, DDIM);

    // 9) out = 2*(h @ W2 + b2)
    tc_gemm<5, false><<<gO, 256, SMEM_BYTES>>>(hbuf, W2, b2, nullptr, nullptr, nullptr,
                                               out, MROWS, DDIM, HDIM);
}

// round 5
// speedup vs baseline: 2.6173x; 2.4568x over previous
#include <cuda_runtime.h>
#include <cuda_bf16.h>
#include <math.h>
#include <stdint.h>

#define BATCH 8
#define TLEN  4096
#define DDIM  512
#define HDIM  1024
#define MROWS (BATCH*TLEN)   // 32768
#define TH    (TLEN*HDIM)    // 2^22

typedef __nv_bfloat16 bf16;

// ---------------- scratch (device globals, no allocation) ----------------
__device__ float g_x1[MROWS*DDIM];
__device__ bf16  g_x1hi[MROWS*DDIM];
__device__ bf16  g_x1lo[MROWS*DDIM];
__device__ bf16  g_x3hi[MROWS*DDIM];
__device__ bf16  g_x3lo[MROWS*DDIM];
__device__ float g_qsig[MROWS*HDIM];
__device__ float g_numer[MROWS*HDIM];
__device__ float g_v[MROWS*HDIM];
__device__ float g_weighted[TH];
__device__ bf16  g_yhi[MROWS*HDIM];
__device__ bf16  g_ylo[MROWS*HDIM];
__device__ float g_x2[MROWS*DDIM];
__device__ bf16  g_hhi[MROWS*HDIM];
__device__ bf16  g_hlo[MROWS*HDIM];
// transposed+split weights: [N,K]
__device__ bf16  g_wq_hi[DDIM*HDIM], g_wq_lo[DDIM*HDIM];
__device__ bf16  g_wk_hi[DDIM*HDIM], g_wk_lo[DDIM*HDIM];
__device__ bf16  g_wv_hi[DDIM*HDIM], g_wv_lo[DDIM*HDIM];
__device__ bf16  g_wo_hi[DDIM*HDIM], g_wo_lo[DDIM*HDIM];
__device__ bf16  g_w1_hi[DDIM*HDIM], g_w1_lo[DDIM*HDIM];
__device__ bf16  g_w2_hi[DDIM*HDIM], g_w2_lo[DDIM*HDIM];

// ================= helpers =================
__device__ __forceinline__ uint32_t smem_u32(const void* p) {
    uint32_t a;
    asm("{ .reg .u64 t; cvta.to.shared.u64 t, %1; cvt.u32.u64 %0, t; }"
        : "=r"(a) : "l"(p));
    return a;
}
__device__ __forceinline__ uint32_t swz128(uint32_t off) {
    return off ^ ((off >> 3) & 0x70);
}
__device__ __forceinline__ void splitf(float a, bf16& hi, bf16& lo) {
    hi = __float2bfloat16_rn(a);
    lo = __float2bfloat16_rn(a - __bfloat162float(hi));
}
__device__ __forceinline__ void ldsm_x4(uint32_t& r0, uint32_t& r1,
                                        uint32_t& r2, uint32_t& r3, uint32_t addr) {
    asm volatile("ldmatrix.sync.aligned.m8n8.x4.shared.b16 {%0,%1,%2,%3}, [%4];"
                 : "=r"(r0), "=r"(r1), "=r"(r2), "=r"(r3) : "r"(addr));
}
__device__ __forceinline__ void mma_bf16(float* d, const uint32_t* a,
                                         uint32_t b0, uint32_t b1) {
    asm volatile("mma.sync.aligned.m16n8k16.row.col.f32.bf16.bf16.f32 "
                 "{%0,%1,%2,%3}, {%4,%5,%6,%7}, {%8,%9}, {%0,%1,%2,%3};"
                 : "+f"(d[0]), "+f"(d[1]), "+f"(d[2]), "+f"(d[3])
                 : "r"(a[0]), "r"(a[1]), "r"(a[2]), "r"(a[3]), "r"(b0), "r"(b1));
}

// ---------------- LayerNorm + split ----------------
template<bool STORE_F32>
__global__ __launch_bounds__(128) void ln_split_kernel(
    const float* __restrict__ x, const float* __restrict__ gamma,
    const float* __restrict__ beta, float* __restrict__ out,
    bf16* __restrict__ ohi, bf16* __restrict__ olo)
{
    const int row = blockIdx.x;
    const int t   = threadIdx.x;
    float4 v = ((const float4*)(x + (size_t)row * DDIM))[t];
    float s  = v.x + v.y + v.z + v.w;
    float ss = v.x*v.x + v.y*v.y + v.z*v.z + v.w*v.w;

    __shared__ float red[2][4];
    const int lane = t & 31, wid = t >> 5;
    #pragma unroll
    for (int o = 16; o > 0; o >>= 1) {
        s  += __shfl_xor_sync(0xffffffffu, s,  o);
        ss += __shfl_xor_sync(0xffffffffu, ss, o);
    }
    if (lane == 0) { red[0][wid] = s; red[1][wid] = ss; }
    __syncthreads();
    s  = red[0][0] + red[0][1] + red[0][2] + red[0][3];
    ss = red[1][0] + red[1][1] + red[1][2] + red[1][3];

    const float mean = s * (1.0f / DDIM);
    const float var  = ss * (1.0f / DDIM) - mean * mean;
    const float rstd = rsqrtf(var + 1e-5f);

    const float4 g4 = ((const float4*)gamma)[t];
    const float4 b4 = ((const float4*)beta)[t];
    float4 o4;
    o4.x = (v.x - mean) * rstd * g4.x + b4.x;
    o4.y = (v.y - mean) * rstd * g4.y + b4.y;
    o4.z = (v.z - mean) * rstd * g4.z + b4.z;
    o4.w = (v.w - mean) * rstd * g4.w + b4.w;
    if (STORE_F32)
        ((float4*)(out + (size_t)row * DDIM))[t] = o4;

    bf16 h[4], l[4];
    splitf(o4.x, h[0], l[0]); splitf(o4.y, h[1], l[1]);
    splitf(o4.z, h[2], l[2]); splitf(o4.w, h[3], l[3]);
    ((uint2*)(ohi + (size_t)row * DDIM))[t] = *(uint2*)h;
    ((uint2*)(olo + (size_t)row * DDIM))[t] = *(uint2*)l;
}

// ---------------- weight transpose + split: W[K,N] -> Wt[N,K] hi/lo --------
__global__ __launch_bounds__(256) void wsplit_kernel(
    const float* __restrict__ W, bf16* __restrict__ Whi, bf16* __restrict__ Wlo,
    int K, int N)
{
    __shared__ float tbuf[32][33];
    const int tx = threadIdx.x & 31;
    const int ty = threadIdx.x >> 5;     // 0..7
    const int n0 = blockIdx.x * 32;
    const int k0 = blockIdx.y * 32;
    #pragma unroll
    for (int i = 0; i < 4; ++i)
        tbuf[ty + i * 8][tx] = W[(size_t)(k0 + ty + i * 8) * N + n0 + tx];
    __syncthreads();
    #pragma unroll
    for (int i = 0; i < 4; ++i) {
        const int n = n0 + ty + i * 8;
        const float v = tbuf[tx][ty + i * 8];
        bf16 h, l;
        splitf(v, h, l);
        Whi[(size_t)n * K + k0 + tx] = h;
        Wlo[(size_t)n * K + k0 + tx] = l;
    }
}

// ---------------- AFT batch reduction ----------------
__global__ __launch_bounds__(256) void aft_reduce_kernel(
    const float* __restrict__ numer, const float* __restrict__ v,
    float* __restrict__ weighted)
{
    const int i = blockIdx.x * blockDim.x + threadIdx.x;
    float den = 0.f, num = 0.f;
    #pragma unroll
    for (int b = 0; b < BATCH; ++b) {
        const size_t idx = (size_t)b * TH + i;
        den += numer[idx];
        num = fmaf(numer[idx], v[idx], num);
    }
    weighted[i] = num / den;
}

// ---------------- Y = qsig .* weighted, split ----------------
__global__ __launch_bounds__(256) void ysplit_kernel(
    const float* __restrict__ qsig, const float* __restrict__ weighted,
    bf16* __restrict__ yhi, bf16* __restrict__ ylo)
{
    const size_t i4 = ((size_t)blockIdx.x * blockDim.x + threadIdx.x) * 4;
    const float4 q = *(const float4*)(qsig + i4);
    const float4 w = *(const float4*)(weighted + (i4 & (TH - 1)));
    bf16 h[4], l[4];
    splitf(q.x * w.x, h[0], l[0]);
    splitf(q.y * w.y, h[1], l[1]);
    splitf(q.z * w.z, h[2], l[2]);
    splitf(q.w * w.w, h[3], l[3]);
    *(uint2*)(yhi + i4) = *(uint2*)h;
    *(uint2*)(ylo + i4) = *(uint2*)l;
}

// ================= HMMA GEMM on pre-split bf16, 3-pass =================
// C[M,N] = (Ahi+Alo)[M,K] * (Bhi+Blo)^T  with B stored [N,K]
// EPI: 0 +bias | 1 sigmoid | 2 exp(+bias+bias2) | 3 +bias+resid | 4 gelu | 5 2*(+bias)
#define TM 128
#define TN 128
#define TK 64

#define SM_A_HI 0
#define SM_A_LO (SM_A_HI + TM*TK*2)
#define SM_B_HI (SM_A_LO + TM*TK*2)
#define SM_B_LO (SM_B_HI + TN*TK*2)
#define SMEM_BYTES (SM_B_LO + TN*TK*2)    // 65536

template<int EPI, bool OUTSPLIT>
__global__ __launch_bounds__(256, 2) void tc_gemm(
    const bf16* __restrict__ Ahi, const bf16* __restrict__ Alo,
    const bf16* __restrict__ Bhi, const bf16* __restrict__ Blo,
    const float* __restrict__ bias, const float* __restrict__ bias2,
    const float* __restrict__ resid,
    float* __restrict__ C, bf16* __restrict__ Chi, bf16* __restrict__ Clo,
    int M, int N, int K)
{
    extern __shared__ char smem[];
    const uint32_t sb  = smem_u32(smem);
    const int tid  = threadIdx.x;
    const int wid  = tid >> 5;
    const int lane = tid & 31;
    const int bm = blockIdx.y * TM;
    const int bn = blockIdx.x * TN;

    const int wm = (wid >> 2) * 64;
    const int wn = (wid & 3) * 32;

    const int rowA = lane & 15;
    const int khA  = lane >> 4;
    const int rowB = (lane & 7) + ((lane >> 4) << 3);
    const int khB  = (lane >> 3) & 1;

    float acc[4][4][4];
    #pragma unroll
    for (int mi = 0; mi < 4; ++mi)
        #pragma unroll
        for (int ni = 0; ni < 4; ++ni)
            #pragma unroll
            for (int r = 0; r < 4; ++r) acc[mi][ni][r] = 0.f;

    // loader mapping: idx -> row (0..127), seg (0..7) of 16B
    const int lrow = tid >> 3;
    const int lseg = (tid & 7) * 8;       // bf16 offset within row
    const uint32_t ldst = swz128((uint32_t)(lrow * 128 + lseg * 2));

    const int nchunks = K / TK;
    for (int c = 0; c < nchunks; ++c) {
        const int k0 = c * TK;

        // ---- copy 4 tiles: each 128 rows x 64 bf16 (=128B rows) ----
        #pragma unroll
        for (int half = 0; half < 4; ++half) {
            const int r = lrow + half * 32;
            const size_t asrc = (size_t)(bm + r) * K + k0 + lseg;
            const size_t bsrc = (size_t)(bn + r) * K + k0 + lseg;
            const uint32_t d = swz128((uint32_t)(r * 128 + lseg * 2));
            *(uint4*)(smem + SM_A_HI + d) = *(const uint4*)(Ahi + asrc);
            *(uint4*)(smem + SM_A_LO + d) = *(const uint4*)(Alo + asrc);
            *(uint4*)(smem + SM_B_HI + d) = *(const uint4*)(Bhi + bsrc);
            *(uint4*)(smem + SM_B_LO + d) = *(const uint4*)(Blo + bsrc);
        }
        __syncthreads();

        // ---- 3 passes with fragment reuse: AhiBhi, AloBhi, AhiBlo ----
        #pragma unroll
        for (int s = 0; s < 4; ++s) {
            uint32_t ah[4][4], al[4][4], bh[2][4], bl[2][4];
            #pragma unroll
            for (int mi = 0; mi < 4; ++mi) {
                const uint32_t off = (uint32_t)((wm + mi * 16 + rowA) * 128
                                                + s * 32 + khA * 16);
                ldsm_x4(ah[mi][0], ah[mi][1], ah[mi][2], ah[mi][3],
                        sb + SM_A_HI + swz128(off));
            }
            #pragma unroll
            for (int nj = 0; nj < 2; ++nj) {
                const uint32_t off = (uint32_t)((wn + nj * 16 + rowB) * 128
                                                + s * 32 + khB * 16);
                ldsm_x4(bh[nj][0], bh[nj][1], bh[nj][2], bh[nj][3],
                        sb + SM_B_HI + swz128(off));
            }
            #pragma unroll
            for (int mi = 0; mi < 4; ++mi)
                #pragma unroll
                for (int ni = 0; ni < 4; ++ni) {
                    const uint32_t* bb = bh[ni >> 1];
                    mma_bf16(acc[mi][ni], ah[mi], bb[(ni & 1) * 2], bb[(ni & 1) * 2 + 1]);
                }
            #pragma unroll
            for (int mi = 0; mi < 4; ++mi) {
                const uint32_t off = (uint32_t)((wm + mi * 16 + rowA) * 128
                                                + s * 32 + khA * 16);
                ldsm_x4(al[mi][0], al[mi][1], al[mi][2], al[mi][3],
                        sb + SM_A_LO + swz128(off));
            }
            #pragma unroll
            for (int mi = 0; mi < 4; ++mi)
                #pragma unroll
                for (int ni = 0; ni < 4; ++ni) {
                    const uint32_t* bb = bh[ni >> 1];
                    mma_bf16(acc[mi][ni], al[mi], bb[(ni & 1) * 2], bb[(ni & 1) * 2 + 1]);
                }
            #pragma unroll
            for (int nj = 0; nj < 2; ++nj) {
                const uint32_t off = (uint32_t)((wn + nj * 16 + rowB) * 128
                                                + s * 32 + khB * 16);
                ldsm_x4(bl[nj][0], bl[nj][1], bl[nj][2], bl[nj][3],
                        sb + SM_B_LO + swz128(off));
            }
            #pragma unroll
            for (int mi = 0; mi < 4; ++mi)
                #pragma unroll
                for (int ni = 0; ni < 4; ++ni) {
                    const uint32_t* bb = bl[ni >> 1];
                    mma_bf16(acc[mi][ni], ah[mi], bb[(ni & 1) * 2], bb[(ni & 1) * 2 + 1]);
                }
        }
        __syncthreads();
    }

    // ---- epilogue ----
    const int qid = lane >> 2;
    const int tc  = (lane & 3) * 2;
    #pragma unroll
    for (int mi = 0; mi < 4; ++mi) {
        #pragma unroll
        for (int half = 0; half < 2; ++half) {
            const int m = bm + wm + mi * 16 + qid + half * 8;
            const float* rrow = (EPI == 3) ? (resid + (size_t)m * N) : nullptr;
            #pragma unroll
            for (int ni = 0; ni < 4; ++ni) {
                const int n = bn + wn + ni * 8 + tc;
                float v0 = acc[mi][ni][half * 2 + 0] + bias[n];
                float v1 = acc[mi][ni][half * 2 + 1] + bias[n + 1];
                if (EPI == 1) {
                    v0 = 1.0f / (1.0f + expf(-v0));
                    v1 = 1.0f / (1.0f + expf(-v1));
                } else if (EPI == 2) {
                    v0 = expf(v0 + bias2[n]);
                    v1 = expf(v1 + bias2[n + 1]);
                } else if (EPI == 3) {
                    v0 += rrow[n];
                    v1 += rrow[n + 1];
                } else if (EPI == 4) {
                    v0 = 0.5f * v0 * (1.0f + erff(v0 * 0.70710678118654752f));
                    v1 = 0.5f * v1 * (1.0f + erff(v1 * 0.70710678118654752f));
                } else if (EPI == 5) {
                    v0 *= 2.0f;
                    v1 *= 2.0f;
                }
                if (OUTSPLIT) {
                    bf16 h0, l0, h1, l1;
                    splitf(v0, h0, l0);
                    splitf(v1, h1, l1);
                    bf16 hp[2] = {h0, h1}, lp[2] = {l0, l1};
                    *(uint32_t*)(Chi + (size_t)m * N + n) = *(uint32_t*)hp;
                    *(uint32_t*)(Clo + (size_t)m * N + n) = *(uint32_t*)lp;
                } else {
                    float2 o; o.x = v0; o.y = v1;
                    *(float2*)(C + (size_t)m * N + n) = o;
                }
            }
        }
    }
}

// ---------------- launch ----------------
extern "C" void kernel_launch(void* const* d_in, const int* in_sizes, int n_in,
                              void* d_out, int out_size)
{
    const float* x     = (const float*)d_in[0];
    const float* gamma = (const float*)d_in[1];
    const float* beta  = (const float*)d_in[2];
    const float* Wq    = (const float*)d_in[3];
    const float* bq    = (const float*)d_in[4];
    const float* Wk    = (const float*)d_in[5];
    const float* bk    = (const float*)d_in[6];
    const float* Wv    = (const float*)d_in[7];
    const float* bv    = (const float*)d_in[8];
    const float* wbias = (const float*)d_in[9];
    const float* Wo    = (const float*)d_in[10];
    const float* bo    = (const float*)d_in[11];
    const float* W1    = (const float*)d_in[12];
    const float* b1    = (const float*)d_in[13];
    const float* W2    = (const float*)d_in[14];
    const float* b2    = (const float*)d_in[15];
    float* out = (float*)d_out;

    float *x1, *qsig, *numer, *vmat, *weighted, *x2;
    bf16 *x1hi, *x1lo, *x3hi, *x3lo, *yhi, *ylo, *hhi, *hlo;
    bf16 *wqh, *wql, *wkh, *wkl, *wvh, *wvl, *woh, *wol, *w1h, *w1l, *w2h, *w2l;
    cudaGetSymbolAddress((void**)&x1,       g_x1);
    cudaGetSymbolAddress((void**)&x1hi,     g_x1hi);
    cudaGetSymbolAddress((void**)&x1lo,     g_x1lo);
    cudaGetSymbolAddress((void**)&x3hi,     g_x3hi);
    cudaGetSymbolAddress((void**)&x3lo,     g_x3lo);
    cudaGetSymbolAddress((void**)&qsig,     g_qsig);
    cudaGetSymbolAddress((void**)&numer,    g_numer);
    cudaGetSymbolAddress((void**)&vmat,     g_v);
    cudaGetSymbolAddress((void**)&weighted, g_weighted);
    cudaGetSymbolAddress((void**)&yhi,      g_yhi);
    cudaGetSymbolAddress((void**)&ylo,      g_ylo);
    cudaGetSymbolAddress((void**)&x2,       g_x2);
    cudaGetSymbolAddress((void**)&hhi,      g_hhi);
    cudaGetSymbolAddress((void**)&hlo,      g_hlo);
    cudaGetSymbolAddress((void**)&wqh, g_wq_hi); cudaGetSymbolAddress((void**)&wql, g_wq_lo);
    cudaGetSymbolAddress((void**)&wkh, g_wk_hi); cudaGetSymbolAddress((void**)&wkl, g_wk_lo);
    cudaGetSymbolAddress((void**)&wvh, g_wv_hi); cudaGetSymbolAddress((void**)&wvl, g_wv_lo);
    cudaGetSymbolAddress((void**)&woh, g_wo_hi); cudaGetSymbolAddress((void**)&wol, g_wo_lo);
    cudaGetSymbolAddress((void**)&w1h, g_w1_hi); cudaGetSymbolAddress((void**)&w1l, g_w1_lo);
    cudaGetSymbolAddress((void**)&w2h, g_w2_hi); cudaGetSymbolAddress((void**)&w2l, g_w2_lo);

    cudaFuncSetAttribute(tc_gemm<0, false>, cudaFuncAttributeMaxDynamicSharedMemorySize, SMEM_BYTES);
    cudaFuncSetAttribute(tc_gemm<1, false>, cudaFuncAttributeMaxDynamicSharedMemorySize, SMEM_BYTES);
    cudaFuncSetAttribute(tc_gemm<2, false>, cudaFuncAttributeMaxDynamicSharedMemorySize, SMEM_BYTES);
    cudaFuncSetAttribute(tc_gemm<3, false>, cudaFuncAttributeMaxDynamicSharedMemorySize, SMEM_BYTES);
    cudaFuncSetAttribute(tc_gemm<4, true >, cudaFuncAttributeMaxDynamicSharedMemorySize, SMEM_BYTES);
    cudaFuncSetAttribute(tc_gemm<5, false>, cudaFuncAttributeMaxDynamicSharedMemorySize, SMEM_BYTES);

    // 0) weight transpose + split (cheap)
    {
        dim3 gDH(HDIM / 32, DDIM / 32);   // K=DDIM, N=HDIM
        dim3 gHD(DDIM / 32, HDIM / 32);   // K=HDIM, N=DDIM
        wsplit_kernel<<<gDH, 256>>>(Wq, wqh, wql, DDIM, HDIM);
        wsplit_kernel<<<gDH, 256>>>(Wk, wkh, wkl, DDIM, HDIM);
        wsplit_kernel<<<gDH, 256>>>(Wv, wvh, wvl, DDIM, HDIM);
        wsplit_kernel<<<gHD, 256>>>(Wo, woh, wol, HDIM, DDIM);
        wsplit_kernel<<<gDH, 256>>>(W1, w1h, w1l, DDIM, HDIM);
        wsplit_kernel<<<gHD, 256>>>(W2, w2h, w2l, HDIM, DDIM);
    }

    // 1) x1 = LN(x), + bf16 split
    ln_split_kernel<true><<<MROWS, 128>>>(x, gamma, beta, x1, x1hi, x1lo);

    // 2-4) Q/K/V GEMMs
    dim3 gQ(HDIM / TN, MROWS / TM);
    tc_gemm<1, false><<<gQ, 256, SMEM_BYTES>>>(x1hi, x1lo, wqh, wql, bq, nullptr,
        nullptr, qsig, nullptr, nullptr, MROWS, HDIM, DDIM);
    tc_gemm<2, false><<<gQ, 256, SMEM_BYTES>>>(x1hi, x1lo, wkh, wkl, bk, wbias,
        nullptr, numer, nullptr, nullptr, MROWS, HDIM, DDIM);
    tc_gemm<0, false><<<gQ, 256, SMEM_BYTES>>>(x1hi, x1lo, wvh, wvl, bv, nullptr,
        nullptr, vmat, nullptr, nullptr, MROWS, HDIM, DDIM);

    // 5) weighted + Y split
    aft_reduce_kernel<<<TH / 256, 256>>>(numer, vmat, weighted);
    ysplit_kernel<<<(MROWS * HDIM) / 1024, 256>>>(qsig, weighted, yhi, ylo);

    // 6) x2 = Y @ Wo + bo + x1
    dim3 gO(DDIM / TN, MROWS / TM);
    tc_gemm<3, false><<<gO, 256, SMEM_BYTES>>>(yhi, ylo, woh, wol, bo, nullptr,
        x1, x2, nullptr, nullptr, MROWS, DDIM, HDIM);

    // 7) x3 = LN(x2) -> bf16 only
    ln_split_kernel<false><<<MROWS, 128>>>(x2, gamma, beta, nullptr, x3hi, x3lo);

    // 8) h = gelu(x3 @ W1 + b1) -> split bf16
    tc_gemm<4, true><<<gQ, 256, SMEM_BYTES>>>(x3hi, x3lo, w1h, w1l, b1, nullptr,
        nullptr, nullptr, hhi, hlo, MROWS, HDIM, DDIM);

    // 9) out = 2*(h @ W2 + b2)
    tc_gemm<5, false><<<gO, 256, SMEM_BYTES>>>(hhi, hlo, w2h, w2l, b2, nullptr,
        nullptr, out, nullptr, nullptr, MROWS, DDIM, HDIM);
}

// round 7
// speedup vs baseline: 2.7772x; 1.0611x over previous
#include <cuda_runtime.h>
#include <cuda_bf16.h>
#include <math.h>
#include <stdint.h>

#define BATCH 8
#define TLEN  4096
#define DDIM  512
#define HDIM  1024
#define MROWS (BATCH*TLEN)   // 32768
#define TH    (TLEN*HDIM)    // 2^22

typedef __nv_bfloat16 bf16;

// ---------------- scratch (device globals, no allocation) ----------------
__device__ float g_x1[MROWS*DDIM];
__device__ bf16  g_x1hi[MROWS*DDIM];
__device__ bf16  g_x1lo[MROWS*DDIM];
__device__ bf16  g_x3hi[MROWS*DDIM];
__device__ bf16  g_x3lo[MROWS*DDIM];
__device__ float g_qsig[MROWS*HDIM];
__device__ float g_numer[MROWS*HDIM];
__device__ float g_v[MROWS*HDIM];
__device__ float g_weighted[TH];
__device__ bf16  g_yhi[MROWS*HDIM];
__device__ bf16  g_ylo[MROWS*HDIM];
__device__ float g_x2[MROWS*DDIM];
__device__ bf16  g_hhi[MROWS*HDIM];
__device__ bf16  g_hlo[MROWS*HDIM];
// transposed+split weights: [N,K]
__device__ bf16  g_wq_hi[DDIM*HDIM], g_wq_lo[DDIM*HDIM];
__device__ bf16  g_wk_hi[DDIM*HDIM], g_wk_lo[DDIM*HDIM];
__device__ bf16  g_wv_hi[DDIM*HDIM], g_wv_lo[DDIM*HDIM];
__device__ bf16  g_wo_hi[DDIM*HDIM], g_wo_lo[DDIM*HDIM];
__device__ bf16  g_w1_hi[DDIM*HDIM], g_w1_lo[DDIM*HDIM];
__device__ bf16  g_w2_hi[DDIM*HDIM], g_w2_lo[DDIM*HDIM];

// ================= helpers =================
__device__ __forceinline__ uint32_t smem_u32(const void* p) {
    uint32_t a;
    asm("{ .reg .u64 t; cvta.to.shared.u64 t, %1; cvt.u32.u64 %0, t; }"
        : "=r"(a) : "l"(p));
    return a;
}
// SW64 swizzle for 64B rows: XOR bits [4:5] with bits [7:8]
__device__ __forceinline__ uint32_t swz64(uint32_t off) {
    return off ^ ((off >> 3) & 0x30);
}
__device__ __forceinline__ void splitf(float a, bf16& hi, bf16& lo) {
    hi = __float2bfloat16_rn(a);
    lo = __float2bfloat16_rn(a - __bfloat162float(hi));
}
__device__ __forceinline__ void ldsm_x4(uint32_t* r, uint32_t addr) {
    asm volatile("ldmatrix.sync.aligned.m8n8.x4.shared.b16 {%0,%1,%2,%3}, [%4];"
                 : "=r"(r[0]), "=r"(r[1]), "=r"(r[2]), "=r"(r[3]) : "r"(addr));
}
__device__ __forceinline__ void mma_bf16(float* d, const uint32_t* a,
                                         uint32_t b0, uint32_t b1) {
    asm volatile("mma.sync.aligned.m16n8k16.row.col.f32.bf16.bf16.f32 "
                 "{%0,%1,%2,%3}, {%4,%5,%6,%7}, {%8,%9}, {%0,%1,%2,%3};"
                 : "+f"(d[0]), "+f"(d[1]), "+f"(d[2]), "+f"(d[3])
                 : "r"(a[0]), "r"(a[1]), "r"(a[2]), "r"(a[3]), "r"(b0), "r"(b1));
}
__device__ __forceinline__ void cp16(uint32_t dst, const void* src) {
    asm volatile("cp.async.cg.shared.global [%0], [%1], 16;" :: "r"(dst), "l"(src));
}
#define CP_COMMIT() asm volatile("cp.async.commit_group;" ::: "memory")
#define CP_WAIT1()  asm volatile("cp.async.wait_group 1;" ::: "memory")
#define CP_WAIT0()  asm volatile("cp.async.wait_group 0;" ::: "memory")

// ---------------- LayerNorm + split ----------------
template<bool STORE_F32>
__global__ __launch_bounds__(128) void ln_split_kernel(
    const float* __restrict__ x, const float* __restrict__ gamma,
    const float* __restrict__ beta, float* __restrict__ out,
    bf16* __restrict__ ohi, bf16* __restrict__ olo)
{
    const int row = blockIdx.x;
    const int t   = threadIdx.x;
    float4 v = ((const float4*)(x + (size_t)row * DDIM))[t];
    float s  = v.x + v.y + v.z + v.w;
    float ss = v.x*v.x + v.y*v.y + v.z*v.z + v.w*v.w;

    __shared__ float red[2][4];
    const int lane = t & 31, wid = t >> 5;
    #pragma unroll
    for (int o = 16; o > 0; o >>= 1) {
        s  += __shfl_xor_sync(0xffffffffu, s,  o);
        ss += __shfl_xor_sync(0xffffffffu, ss, o);
    }
    if (lane == 0) { red[0][wid] = s; red[1][wid] = ss; }
    __syncthreads();
    s  = red[0][0] + red[0][1] + red[0][2] + red[0][3];
    ss = red[1][0] + red[1][1] + red[1][2] + red[1][3];

    const float mean = s * (1.0f / DDIM);
    const float var  = ss * (1.0f / DDIM) - mean * mean;
    const float rstd = rsqrtf(var + 1e-5f);

    const float4 g4 = ((const float4*)gamma)[t];
    const float4 b4 = ((const float4*)beta)[t];
    float4 o4;
    o4.x = (v.x - mean) * rstd * g4.x + b4.x;
    o4.y = (v.y - mean) * rstd * g4.y + b4.y;
    o4.z = (v.z - mean) * rstd * g4.z + b4.z;
    o4.w = (v.w - mean) * rstd * g4.w + b4.w;
    if (STORE_F32)
        ((float4*)(out + (size_t)row * DDIM))[t] = o4;

    bf16 h[4], l[4];
    splitf(o4.x, h[0], l[0]); splitf(o4.y, h[1], l[1]);
    splitf(o4.z, h[2], l[2]); splitf(o4.w, h[3], l[3]);
    ((uint2*)(ohi + (size_t)row * DDIM))[t] = *(uint2*)h;
    ((uint2*)(olo + (size_t)row * DDIM))[t] = *(uint2*)l;
}

// ---------------- weight transpose + split: W[K,N] -> Wt[N,K] hi/lo --------
__global__ __launch_bounds__(256) void wsplit_kernel(
    const float* __restrict__ W, bf16* __restrict__ Whi, bf16* __restrict__ Wlo,
    int K, int N)
{
    __shared__ float tbuf[32][33];
    const int tx = threadIdx.x & 31;
    const int ty = threadIdx.x >> 5;
    const int n0 = blockIdx.x * 32;
    const int k0 = blockIdx.y * 32;
    #pragma unroll
    for (int i = 0; i < 4; ++i)
        tbuf[ty + i * 8][tx] = W[(size_t)(k0 + ty + i * 8) * N + n0 + tx];
    __syncthreads();
    #pragma unroll
    for (int i = 0; i < 4; ++i) {
        const int n = n0 + ty + i * 8;
        bf16 h, l;
        splitf(tbuf[tx][ty + i * 8], h, l);
        Whi[(size_t)n * K + k0 + tx] = h;
        Wlo[(size_t)n * K + k0 + tx] = l;
    }
}

// ---------------- AFT batch reduction ----------------
__global__ __launch_bounds__(256) void aft_reduce_kernel(
    const float* __restrict__ numer, const float* __restrict__ v,
    float* __restrict__ weighted)
{
    const int i = blockIdx.x * blockDim.x + threadIdx.x;
    float den = 0.f, num = 0.f;
    #pragma unroll
    for (int b = 0; b < BATCH; ++b) {
        const size_t idx = (size_t)b * TH + i;
        den += numer[idx];
        num = fmaf(numer[idx], v[idx], num);
    }
    weighted[i] = num / den;
}

// ---------------- Y = qsig .* weighted, split ----------------
__global__ __launch_bounds__(256) void ysplit_kernel(
    const float* __restrict__ qsig, const float* __restrict__ weighted,
    bf16* __restrict__ yhi, bf16* __restrict__ ylo)
{
    const size_t i4 = ((size_t)blockIdx.x * blockDim.x + threadIdx.x) * 4;
    const float4 q = *(const float4*)(qsig + i4);
    const float4 w = *(const float4*)(weighted + (i4 & (TH - 1)));
    bf16 h[4], l[4];
    splitf(q.x * w.x, h[0], l[0]);
    splitf(q.y * w.y, h[1], l[1]);
    splitf(q.z * w.z, h[2], l[2]);
    splitf(q.w * w.w, h[3], l[3]);
    *(uint2*)(yhi + i4) = *(uint2*)h;
    *(uint2*)(ylo + i4) = *(uint2*)l;
}

// ================= HMMA GEMM, cp.async double-buffered, 3-pass =================
// C[M,N] = (Ahi+Alo)[M,K] * (Bhi+Blo)^T  with B stored [N,K]
// EPI: 0 +bias | 1 sigmoid | 2 exp(+bias+bias2) | 3 +bias+resid | 4 gelu | 5 2*(+bias)
#define TM 128
#define TN 128
#define TK 32

// per-stage layout: 4 tiles of 128 rows x 32 bf16 (64B rows, SW64 swizzle)
#define T_A_HI 0
#define T_A_LO 8192
#define T_B_HI 16384
#define T_B_LO 24576
#define STAGE  32768
#define SMEM_BYTES (2*STAGE)   // 65536

template<int EPI, bool OUTSPLIT>
__global__ __launch_bounds__(256, 2) void tc_gemm(
    const bf16* __restrict__ Ahi, const bf16* __restrict__ Alo,
    const bf16* __restrict__ Bhi, const bf16* __restrict__ Blo,
    const float* __restrict__ bias, const float* __restrict__ bias2,
    const float* __restrict__ resid,
    float* __restrict__ C, bf16* __restrict__ Chi, bf16* __restrict__ Clo,
    int M, int N, int K)
{
    extern __shared__ char smem[];
    const uint32_t sb  = smem_u32(smem);
    const int tid  = threadIdx.x;
    const int wid  = tid >> 5;
    const int lane = tid & 31;
    const int bm = blockIdx.y * TM;
    const int bn = blockIdx.x * TN;

    const int wm = (wid >> 2) * 64;      // warp tile 64x32
    const int wn = (wid & 3) * 32;

    const int rowA = lane & 15;
    const int khA  = lane >> 4;
    const int rowB = (lane & 7) + ((lane >> 4) << 3);
    const int khB  = (lane >> 3) & 1;

    float acc[4][4][4];
    #pragma unroll
    for (int mi = 0; mi < 4; ++mi)
        #pragma unroll
        for (int ni = 0; ni < 4; ++ni)
            #pragma unroll
            for (int r = 0; r < 4; ++r) acc[mi][ni][r] = 0.f;

    // cp.async mapping: thread -> (row, 16B seg)
    const int lr = tid >> 2;             // 0..63
    const int ls = tid & 3;              // seg 0..3

    const int nchunks = K / TK;

    // prefetch chunk 0
    {
        const uint32_t base = sb;
        #pragma unroll
        for (int h = 0; h < 2; ++h) {
            const int r = lr + h * 64;
            const uint32_t so = swz64((uint32_t)(r * 64 + ls * 16));
            const size_t asrc = (size_t)(bm + r) * K + ls * 8;
            const size_t bsrc = (size_t)(bn + r) * K + ls * 8;
            cp16(base + T_A_HI + so, Ahi + asrc);
            cp16(base + T_A_LO + so, Alo + asrc);
            cp16(base + T_B_HI + so, Bhi + bsrc);
            cp16(base + T_B_LO + so, Blo + bsrc);
        }
        CP_COMMIT();
    }

    for (int c = 0; c < nchunks; ++c) {
        // prefetch chunk c+1
        if (c + 1 < nchunks) {
            const uint32_t base = sb + ((c + 1) & 1) * STAGE;
            const int k0 = (c + 1) * TK;
            #pragma unroll
            for (int h = 0; h < 2; ++h) {
                const int r = lr + h * 64;
                const uint32_t so = swz64((uint32_t)(r * 64 + ls * 16));
                const size_t asrc = (size_t)(bm + r) * K + k0 + ls * 8;
                const size_t bsrc = (size_t)(bn + r) * K + k0 + ls * 8;
                cp16(base + T_A_HI + so, Ahi + asrc);
                cp16(base + T_A_LO + so, Alo + asrc);
                cp16(base + T_B_HI + so, Bhi + bsrc);
                cp16(base + T_B_LO + so, Blo + bsrc);
            }
            CP_COMMIT();
            CP_WAIT1();
        } else {
            CP_WAIT0();
        }
        __syncthreads();

        const uint32_t buf = sb + (c & 1) * STAGE;
        #pragma unroll
        for (int s = 0; s < 2; ++s) {
            uint32_t ah[4][4], bh[2][4], t[4][4];
            #pragma unroll
            for (int mi = 0; mi < 4; ++mi) {
                const uint32_t off = (uint32_t)((wm + mi * 16 + rowA) * 64
                                                + s * 32 + khA * 16);
                ldsm_x4(ah[mi], buf + T_A_HI + swz64(off));
            }
            #pragma unroll
            for (int nj = 0; nj < 2; ++nj) {
                const uint32_t off = (uint32_t)((wn + nj * 16 + rowB) * 64
                                                + s * 32 + khB * 16);
                ldsm_x4(bh[nj], buf + T_B_HI + swz64(off));
            }
            // pass1: Ahi * Bhi
            #pragma unroll
            for (int mi = 0; mi < 4; ++mi)
                #pragma unroll
                for (int ni = 0; ni < 4; ++ni) {
                    const uint32_t* bb = bh[ni >> 1];
                    mma_bf16(acc[mi][ni], ah[mi], bb[(ni & 1) * 2], bb[(ni & 1) * 2 + 1]);
                }
            // pass2: Alo * Bhi
            #pragma unroll
            for (int mi = 0; mi < 4; ++mi) {
                const uint32_t off = (uint32_t)((wm + mi * 16 + rowA) * 64
                                                + s * 32 + khA * 16);
                ldsm_x4(t[mi], buf + T_A_LO + swz64(off));
            }
            #pragma unroll
            for (int mi = 0; mi < 4; ++mi)
                #pragma unroll
                for (int ni = 0; ni < 4; ++ni) {
                    const uint32_t* bb = bh[ni >> 1];
                    mma_bf16(acc[mi][ni], t[mi], bb[(ni & 1) * 2], bb[(ni & 1) * 2 + 1]);
                }
            // pass3: Ahi * Blo (reuse t[0..1] for Blo frags)
            #pragma unroll
            for (int nj = 0; nj < 2; ++nj) {
                const uint32_t off = (uint32_t)((wn + nj * 16 + rowB) * 64
                                                + s * 32 + khB * 16);
                ldsm_x4(t[nj], buf + T_B_LO + swz64(off));
            }
            #pragma unroll
            for (int mi = 0; mi < 4; ++mi)
                #pragma unroll
                for (int ni = 0; ni < 4; ++ni) {
                    const uint32_t* bb = t[ni >> 1];
                    mma_bf16(acc[mi][ni], ah[mi], bb[(ni & 1) * 2], bb[(ni & 1) * 2 + 1]);
                }
        }
        __syncthreads();
    }

    // ---- epilogue ----
    const int qid = lane >> 2;
    const int tc  = (lane & 3) * 2;
    #pragma unroll
    for (int mi = 0; mi < 4; ++mi) {
        #pragma unroll
        for (int half = 0; half < 2; ++half) {
            const int m = bm + wm + mi * 16 + qid + half * 8;
            const float* rrow = (EPI == 3) ? (resid + (size_t)m * N) : nullptr;
            #pragma unroll
            for (int ni = 0; ni < 4; ++ni) {
                const int n = bn + wn + ni * 8 + tc;
                float v0 = acc[mi][ni][half * 2 + 0] + bias[n];
                float v1 = acc[mi][ni][half * 2 + 1] + bias[n + 1];
                if (EPI == 1) {
                    v0 = 1.0f / (1.0f + expf(-v0));
                    v1 = 1.0f / (1.0f + expf(-v1));
                } else if (EPI == 2) {
                    v0 = expf(v0 + bias2[n]);
                    v1 = expf(v1 + bias2[n + 1]);
                } else if (EPI == 3) {
                    v0 += rrow[n];
                    v1 += rrow[n + 1];
                } else if (EPI == 4) {
                    v0 = 0.5f * v0 * (1.0f + erff(v0 * 0.70710678118654752f));
                    v1 = 0.5f * v1 * (1.0f + erff(v1 * 0.70710678118654752f));
                } else if (EPI == 5) {
                    v0 *= 2.0f;
                    v1 *= 2.0f;
                }
                if (OUTSPLIT) {
                    bf16 h0, l0, h1, l1;
                    splitf(v0, h0, l0);
                    splitf(v1, h1, l1);
                    bf16 hp[2] = {h0, h1}, lp[2] = {l0, l1};
                    *(uint32_t*)(Chi + (size_t)m * N + n) = *(uint32_t*)hp;
                    *(uint32_t*)(Clo + (size_t)m * N + n) = *(uint32_t*)lp;
                } else {
                    float2 o; o.x = v0; o.y = v1;
                    *(float2*)(C + (size_t)m * N + n) = o;
                }
            }
        }
    }
}

// ---------------- launch ----------------
extern "C" void kernel_launch(void* const* d_in, const int* in_sizes, int n_in,
                              void* d_out, int out_size)
{
    const float* x     = (const float*)d_in[0];
    const float* gamma = (const float*)d_in[1];
    const float* beta  = (const float*)d_in[2];
    const float* Wq    = (const float*)d_in[3];
    const float* bq    = (const float*)d_in[4];
    const float* Wk    = (const float*)d_in[5];
    const float* bk    = (const float*)d_in[6];
    const float* Wv    = (const float*)d_in[7];
    const float* bv    = (const float*)d_in[8];
    const float* wbias = (const float*)d_in[9];
    const float* Wo    = (const float*)d_in[10];
    const float* bo    = (const float*)d_in[11];
    const float* W1    = (const float*)d_in[12];
    const float* b1    = (const float*)d_in[13];
    const float* W2    = (const float*)d_in[14];
    const float* b2    = (const float*)d_in[15];
    float* out = (float*)d_out;

    float *x1, *qsig, *numer, *vmat, *weighted, *x2;
    bf16 *x1hi, *x1lo, *x3hi, *x3lo, *yhi, *ylo, *hhi, *hlo;
    bf16 *wqh, *wql, *wkh, *wkl, *wvh, *wvl, *woh, *wol, *w1h, *w1l, *w2h, *w2l;
    cudaGetSymbolAddress((void**)&x1,       g_x1);
    cudaGetSymbolAddress((void**)&x1hi,     g_x1hi);
    cudaGetSymbolAddress((void**)&x1lo,     g_x1lo);
    cudaGetSymbolAddress((void**)&x3hi,     g_x3hi);
    cudaGetSymbolAddress((void**)&x3lo,     g_x3lo);
    cudaGetSymbolAddress((void**)&qsig,     g_qsig);
    cudaGetSymbolAddress((void**)&numer,    g_numer);
    cudaGetSymbolAddress((void**)&vmat,     g_v);
    cudaGetSymbolAddress((void**)&weighted, g_weighted);
    cudaGetSymbolAddress((void**)&yhi,      g_yhi);
    cudaGetSymbolAddress((void**)&ylo,      g_ylo);
    cudaGetSymbolAddress((void**)&x2,       g_x2);
    cudaGetSymbolAddress((void**)&hhi,      g_hhi);
    cudaGetSymbolAddress((void**)&hlo,      g_hlo);
    cudaGetSymbolAddress((void**)&wqh, g_wq_hi); cudaGetSymbolAddress((void**)&wql, g_wq_lo);
    cudaGetSymbolAddress((void**)&wkh, g_wk_hi); cudaGetSymbolAddress((void**)&wkl, g_wk_lo);
    cudaGetSymbolAddress((void**)&wvh, g_wv_hi); cudaGetSymbolAddress((void**)&wvl, g_wv_lo);
    cudaGetSymbolAddress((void**)&woh, g_wo_hi); cudaGetSymbolAddress((void**)&wol, g_wo_lo);
    cudaGetSymbolAddress((void**)&w1h, g_w1_hi); cudaGetSymbolAddress((void**)&w1l, g_w1_lo);
    cudaGetSymbolAddress((void**)&w2h, g_w2_hi); cudaGetSymbolAddress((void**)&w2l, g_w2_lo);

    cudaFuncSetAttribute(tc_gemm<0, false>, cudaFuncAttributeMaxDynamicSharedMemorySize, SMEM_BYTES);
    cudaFuncSetAttribute(tc_gemm<1, false>, cudaFuncAttributeMaxDynamicSharedMemorySize, SMEM_BYTES);
    cudaFuncSetAttribute(tc_gemm<2, false>, cudaFuncAttributeMaxDynamicSharedMemorySize, SMEM_BYTES);
    cudaFuncSetAttribute(tc_gemm<3, false>, cudaFuncAttributeMaxDynamicSharedMemorySize, SMEM_BYTES);
    cudaFuncSetAttribute(tc_gemm<4, true >, cudaFuncAttributeMaxDynamicSharedMemorySize, SMEM_BYTES);
    cudaFuncSetAttribute(tc_gemm<5, false>, cudaFuncAttributeMaxDynamicSharedMemorySize, SMEM_BYTES);

    // 0) weight transpose + split (cheap)
    {
        dim3 gDH(HDIM / 32, DDIM / 32);
        dim3 gHD(DDIM / 32, HDIM / 32);
        wsplit_kernel<<<gDH, 256>>>(Wq, wqh, wql, DDIM, HDIM);
        wsplit_kernel<<<gDH, 256>>>(Wk, wkh, wkl, DDIM, HDIM);
        wsplit_kernel<<<gDH, 256>>>(Wv, wvh, wvl, DDIM, HDIM);
        wsplit_kernel<<<gHD, 256>>>(Wo, woh, wol, HDIM, DDIM);
        wsplit_kernel<<<gDH, 256>>>(W1, w1h, w1l, DDIM, HDIM);
        wsplit_kernel<<<gHD, 256>>>(W2, w2h, w2l, HDIM, DDIM);
    }

    // 1) x1 = LN(x), + bf16 split
    ln_split_kernel<true><<<MROWS, 128>>>(x, gamma, beta, x1, x1hi, x1lo);

    // 2-4) Q/K/V GEMMs
    dim3 gQ(HDIM / TN, MROWS / TM);
    tc_gemm<1, false><<<gQ, 256, SMEM_BYTES>>>(x1hi, x1lo, wqh, wql, bq, nullptr,
        nullptr, qsig, nullptr, nullptr, MROWS, HDIM, DDIM);
    tc_gemm<2, false><<<gQ, 256, SMEM_BYTES>>>(x1hi, x1lo, wkh, wkl, bk, wbias,
        nullptr, numer, nullptr, nullptr, MROWS, HDIM, DDIM);
    tc_gemm<0, false><<<gQ, 256, SMEM_BYTES>>>(x1hi, x1lo, wvh, wvl, bv, nullptr,
        nullptr, vmat, nullptr, nullptr, MROWS, HDIM, DDIM);

    // 5) weighted + Y split
    aft_reduce_kernel<<<TH / 256, 256>>>(numer, vmat, weighted);
    ysplit_kernel<<<(MROWS * HDIM) / 1024, 256>>>(qsig, weighted, yhi, ylo);

    // 6) x2 = Y @ Wo + bo + x1
    dim3 gO(DDIM / TN, MROWS / TM);
    tc_gemm<3, false><<<gO, 256, SMEM_BYTES>>>(yhi, ylo, woh, wol, bo, nullptr,
        x1, x2, nullptr, nullptr, MROWS, DDIM, HDIM);

    // 7) x3 = LN(x2) -> bf16 only
    ln_split_kernel<false><<<MROWS, 128>>>(x2, gamma, beta, nullptr, x3hi, x3lo);

    // 8) h = gelu(x3 @ W1 + b1) -> split bf16
    tc_gemm<4, true><<<gQ, 256, SMEM_BYTES>>>(x3hi, x3lo, w1h, w1l, b1, nullptr,
        nullptr, nullptr, hhi, hlo, MROWS, HDIM, DDIM);

    // 9) out = 2*(h @ W2 + b2)
    tc_gemm<5, false><<<gO, 256, SMEM_BYTES>>>(hhi, hlo, w2h, w2l, b2, nullptr,
        nullptr, out, nullptr, nullptr, MROWS, DDIM, HDIM);
}

// round 8
// speedup vs baseline: 2.8397x; 1.0225x over previous
#include <cuda_runtime.h>
#include <cuda_bf16.h>
#include <math.h>
#include <stdint.h>

#define BATCH 8
#define TLEN  4096
#define DDIM  512
#define HDIM  1024
#define MROWS (BATCH*TLEN)   // 32768
#define TH    (TLEN*HDIM)    // 2^22

typedef __nv_bfloat16 bf16;

// ---------------- scratch (device globals, no allocation) ----------------
__device__ float g_x1[MROWS*DDIM];
__device__ bf16  g_x1hi[MROWS*DDIM];
__device__ bf16  g_x1lo[MROWS*DDIM];
__device__ bf16  g_x3hi[MROWS*DDIM];
__device__ bf16  g_x3lo[MROWS*DDIM];
__device__ float g_qsig[MROWS*HDIM];
__device__ float g_numer[MROWS*HDIM];
__device__ float g_v[MROWS*HDIM];
__device__ bf16  g_yhi[MROWS*HDIM];
__device__ bf16  g_ylo[MROWS*HDIM];
__device__ float g_x2[MROWS*DDIM];
__device__ bf16  g_hhi[MROWS*HDIM];
__device__ bf16  g_hlo[MROWS*HDIM];
// transposed+split weights: [N,K]
__device__ bf16  g_wq_hi[DDIM*HDIM], g_wq_lo[DDIM*HDIM];
__device__ bf16  g_wk_hi[DDIM*HDIM], g_wk_lo[DDIM*HDIM];
__device__ bf16  g_wv_hi[DDIM*HDIM], g_wv_lo[DDIM*HDIM];
__device__ bf16  g_wo_hi[DDIM*HDIM], g_wo_lo[DDIM*HDIM];
__device__ bf16  g_w1_hi[DDIM*HDIM], g_w1_lo[DDIM*HDIM];
__device__ bf16  g_w2_hi[DDIM*HDIM], g_w2_lo[DDIM*HDIM];

// ================= helpers =================
__device__ __forceinline__ uint32_t smem_u32(const void* p) {
    uint32_t a;
    asm("{ .reg .u64 t; cvta.to.shared.u64 t, %1; cvt.u32.u64 %0, t; }"
        : "=r"(a) : "l"(p));
    return a;
}
// SW64 swizzle for 64B rows
__device__ __forceinline__ uint32_t swz64(uint32_t off) {
    return off ^ ((off >> 3) & 0x30);
}
__device__ __forceinline__ void splitf(float a, bf16& hi, bf16& lo) {
    hi = __float2bfloat16_rn(a);
    lo = __float2bfloat16_rn(a - __bfloat162float(hi));
}
__device__ __forceinline__ void ldsm_x4(uint32_t* r, uint32_t addr) {
    asm volatile("ldmatrix.sync.aligned.m8n8.x4.shared.b16 {%0,%1,%2,%3}, [%4];"
                 : "=r"(r[0]), "=r"(r[1]), "=r"(r[2]), "=r"(r[3]) : "r"(addr));
}
__device__ __forceinline__ void mma_bf16(float* d, const uint32_t* a,
                                         uint32_t b0, uint32_t b1) {
    asm volatile("mma.sync.aligned.m16n8k16.row.col.f32.bf16.bf16.f32 "
                 "{%0,%1,%2,%3}, {%4,%5,%6,%7}, {%8,%9}, {%0,%1,%2,%3};"
                 : "+f"(d[0]), "+f"(d[1]), "+f"(d[2]), "+f"(d[3])
                 : "r"(a[0]), "r"(a[1]), "r"(a[2]), "r"(a[3]), "r"(b0), "r"(b1));
}
__device__ __forceinline__ void cp16(uint32_t dst, const void* src) {
    asm volatile("cp.async.cg.shared.global [%0], [%1], 16;" :: "r"(dst), "l"(src));
}
#define CP_COMMIT() asm volatile("cp.async.commit_group;" ::: "memory")
#define CP_WAIT1()  asm volatile("cp.async.wait_group 1;" ::: "memory")
#define CP_WAIT0()  asm volatile("cp.async.wait_group 0;" ::: "memory")

// ---------------- LayerNorm + split ----------------
template<bool STORE_F32>
__global__ __launch_bounds__(128) void ln_split_kernel(
    const float* __restrict__ x, const float* __restrict__ gamma,
    const float* __restrict__ beta, float* __restrict__ out,
    bf16* __restrict__ ohi, bf16* __restrict__ olo)
{
    const int row = blockIdx.x;
    const int t   = threadIdx.x;
    float4 v = ((const float4*)(x + (size_t)row * DDIM))[t];
    float s  = v.x + v.y + v.z + v.w;
    float ss = v.x*v.x + v.y*v.y + v.z*v.z + v.w*v.w;

    __shared__ float red[2][4];
    const int lane = t & 31, wid = t >> 5;
    #pragma unroll
    for (int o = 16; o > 0; o >>= 1) {
        s  += __shfl_xor_sync(0xffffffffu, s,  o);
        ss += __shfl_xor_sync(0xffffffffu, ss, o);
    }
    if (lane == 0) { red[0][wid] = s; red[1][wid] = ss; }
    __syncthreads();
    s  = red[0][0] + red[0][1] + red[0][2] + red[0][3];
    ss = red[1][0] + red[1][1] + red[1][2] + red[1][3];

    const float mean = s * (1.0f / DDIM);
    const float var  = ss * (1.0f / DDIM) - mean * mean;
    const float rstd = rsqrtf(var + 1e-5f);

    const float4 g4 = ((const float4*)gamma)[t];
    const float4 b4 = ((const float4*)beta)[t];
    float4 o4;
    o4.x = (v.x - mean) * rstd * g4.x + b4.x;
    o4.y = (v.y - mean) * rstd * g4.y + b4.y;
    o4.z = (v.z - mean) * rstd * g4.z + b4.z;
    o4.w = (v.w - mean) * rstd * g4.w + b4.w;
    if (STORE_F32)
        ((float4*)(out + (size_t)row * DDIM))[t] = o4;

    bf16 h[4], l[4];
    splitf(o4.x, h[0], l[0]); splitf(o4.y, h[1], l[1]);
    splitf(o4.z, h[2], l[2]); splitf(o4.w, h[3], l[3]);
    ((uint2*)(ohi + (size_t)row * DDIM))[t] = *(uint2*)h;
    ((uint2*)(olo + (size_t)row * DDIM))[t] = *(uint2*)l;
}

// ---------------- weight transpose + split: W[K,N] -> Wt[N,K] hi/lo --------
__global__ __launch_bounds__(256) void wsplit_kernel(
    const float* __restrict__ W, bf16* __restrict__ Whi, bf16* __restrict__ Wlo,
    int K, int N)
{
    __shared__ float tbuf[32][33];
    const int tx = threadIdx.x & 31;
    const int ty = threadIdx.x >> 5;
    const int n0 = blockIdx.x * 32;
    const int k0 = blockIdx.y * 32;
    #pragma unroll
    for (int i = 0; i < 4; ++i)
        tbuf[ty + i * 8][tx] = W[(size_t)(k0 + ty + i * 8) * N + n0 + tx];
    __syncthreads();
    #pragma unroll
    for (int i = 0; i < 4; ++i) {
        const int n = n0 + ty + i * 8;
        bf16 h, l;
        splitf(tbuf[tx][ty + i * 8], h, l);
        Whi[(size_t)n * K + k0 + tx] = h;
        Wlo[(size_t)n * K + k0 + tx] = l;
    }
}

// ------- fused AFT reduction + Y split: y = sigmoidQ .* (sum nV / sum n) ----
__global__ __launch_bounds__(256) void aft_ysplit_kernel(
    const float* __restrict__ numer, const float* __restrict__ v,
    const float* __restrict__ qsig,
    bf16* __restrict__ yhi, bf16* __restrict__ ylo)
{
    const size_t i4 = ((size_t)blockIdx.x * blockDim.x + threadIdx.x) * 4;
    float4 den = make_float4(0.f, 0.f, 0.f, 0.f);
    float4 num = make_float4(0.f, 0.f, 0.f, 0.f);
    #pragma unroll
    for (int b = 0; b < BATCH; ++b) {
        const float4 n4 = *(const float4*)(numer + (size_t)b * TH + i4);
        const float4 v4 = *(const float4*)(v     + (size_t)b * TH + i4);
        den.x += n4.x; den.y += n4.y; den.z += n4.z; den.w += n4.w;
        num.x = fmaf(n4.x, v4.x, num.x);
        num.y = fmaf(n4.y, v4.y, num.y);
        num.z = fmaf(n4.z, v4.z, num.z);
        num.w = fmaf(n4.w, v4.w, num.w);
    }
    const float4 w = make_float4(num.x / den.x, num.y / den.y,
                                 num.z / den.z, num.w / den.w);
    #pragma unroll
    for (int b = 0; b < BATCH; ++b) {
        const size_t idx = (size_t)b * TH + i4;
        const float4 q = *(const float4*)(qsig + idx);
        bf16 h[4], l[4];
        splitf(q.x * w.x, h[0], l[0]);
        splitf(q.y * w.y, h[1], l[1]);
        splitf(q.z * w.z, h[2], l[2]);
        splitf(q.w * w.w, h[3], l[3]);
        *(uint2*)(yhi + idx) = *(uint2*)h;
        *(uint2*)(ylo + idx) = *(uint2*)l;
    }
}

// ================= HMMA GEMM, 3-stage cp.async pipeline, 3-pass =================
// C[M,N] = (Ahi+Alo)[M,K] * (Bhi+Blo)^T  with B stored [N,K]
// EPI: 0 +bias | 1 sigmoid | 2 exp(+bias+bias2) | 3 +bias+resid | 4 gelu | 5 2*(+bias)
#define TM 128
#define TN 128
#define TK 32

#define T_A_HI 0
#define T_A_LO 8192
#define T_B_HI 16384
#define T_B_LO 24576
#define STAGE  32768
#define NSTG   3
#define SMEM_BYTES (NSTG*STAGE)   // 98304

template<int EPI, bool OUTSPLIT>
__global__ __launch_bounds__(256, 2) void tc_gemm(
    const bf16* __restrict__ Ahi, const bf16* __restrict__ Alo,
    const bf16* __restrict__ Bhi, const bf16* __restrict__ Blo,
    const float* __restrict__ bias, const float* __restrict__ bias2,
    const float* __restrict__ resid,
    float* __restrict__ C, bf16* __restrict__ Chi, bf16* __restrict__ Clo,
    int M, int N, int K)
{
    extern __shared__ char smem[];
    const uint32_t sb  = smem_u32(smem);
    const int tid  = threadIdx.x;
    const int wid  = tid >> 5;
    const int lane = tid & 31;
    const int bm = blockIdx.y * TM;
    const int bn = blockIdx.x * TN;

    const int wm = (wid >> 2) * 64;      // warp tile 64x32
    const int wn = (wid & 3) * 32;

    const int rowA = lane & 15;
    const int khA  = lane >> 4;
    const int rowB = (lane & 7) + ((lane >> 4) << 3);
    const int khB  = (lane >> 3) & 1;

    float acc[4][4][4];
    #pragma unroll
    for (int mi = 0; mi < 4; ++mi)
        #pragma unroll
        for (int ni = 0; ni < 4; ++ni)
            #pragma unroll
            for (int r = 0; r < 4; ++r) acc[mi][ni][r] = 0.f;

    // cp.async mapping: thread -> (row, 16B seg)
    const int lr = tid >> 2;             // 0..63
    const int ls = tid & 3;              // seg 0..3

    const int nchunks = K / TK;

    auto prefetch = [&](int chunk, uint32_t base) {
        const int k0 = chunk * TK;
        #pragma unroll
        for (int h = 0; h < 2; ++h) {
            const int r = lr + h * 64;
            const uint32_t so = swz64((uint32_t)(r * 64 + ls * 16));
            const size_t asrc = (size_t)(bm + r) * K + k0 + ls * 8;
            const size_t bsrc = (size_t)(bn + r) * K + k0 + ls * 8;
            cp16(base + T_A_HI + so, Ahi + asrc);
            cp16(base + T_A_LO + so, Alo + asrc);
            cp16(base + T_B_HI + so, Bhi + bsrc);
            cp16(base + T_B_LO + so, Blo + bsrc);
        }
    };

    // prologue: chunks 0 and 1 in flight
    prefetch(0, sb);
    CP_COMMIT();
    if (nchunks > 1) {
        prefetch(1, sb + STAGE);
        CP_COMMIT();
    }

    int cst = 0;   // stage of chunk c
    int pst = 2;   // stage of chunk c+2
    for (int c = 0; c < nchunks; ++c) {
        if (c < nchunks - 1) CP_WAIT1(); else CP_WAIT0();
        __syncthreads();   // chunk c visible to all; all warps done with chunk c-1

        if (c + 2 < nchunks) {
            prefetch(c + 2, sb + pst * STAGE);
            CP_COMMIT();
            pst = (pst + 1 == NSTG) ? 0 : pst + 1;
        }

        const uint32_t buf = sb + cst * STAGE;
        cst = (cst + 1 == NSTG) ? 0 : cst + 1;

        #pragma unroll
        for (int s = 0; s < 2; ++s) {
            uint32_t ah[4][4], bh[2][4], t[4][4];
            #pragma unroll
            for (int mi = 0; mi < 4; ++mi) {
                const uint32_t off = (uint32_t)((wm + mi * 16 + rowA) * 64
                                                + s * 32 + khA * 16);
                ldsm_x4(ah[mi], buf + T_A_HI + swz64(off));
            }
            #pragma unroll
            for (int nj = 0; nj < 2; ++nj) {
                const uint32_t off = (uint32_t)((wn + nj * 16 + rowB) * 64
                                                + s * 32 + khB * 16);
                ldsm_x4(bh[nj], buf + T_B_HI + swz64(off));
            }
            // pass1: Ahi * Bhi
            #pragma unroll
            for (int mi = 0; mi < 4; ++mi)
                #pragma unroll
                for (int ni = 0; ni < 4; ++ni) {
                    const uint32_t* bb = bh[ni >> 1];
                    mma_bf16(acc[mi][ni], ah[mi], bb[(ni & 1) * 2], bb[(ni & 1) * 2 + 1]);
                }
            // pass2: Alo * Bhi
            #pragma unroll
            for (int mi = 0; mi < 4; ++mi) {
                const uint32_t off = (uint32_t)((wm + mi * 16 + rowA) * 64
                                                + s * 32 + khA * 16);
                ldsm_x4(t[mi], buf + T_A_LO + swz64(off));
            }
            #pragma unroll
            for (int mi = 0; mi < 4; ++mi)
                #pragma unroll
                for (int ni = 0; ni < 4; ++ni) {
                    const uint32_t* bb = bh[ni >> 1];
                    mma_bf16(acc[mi][ni], t[mi], bb[(ni & 1) * 2], bb[(ni & 1) * 2 + 1]);
                }
            // pass3: Ahi * Blo
            #pragma unroll
            for (int nj = 0; nj < 2; ++nj) {
                const uint32_t off = (uint32_t)((wn + nj * 16 + rowB) * 64
                                                + s * 32 + khB * 16);
                ldsm_x4(t[nj], buf + T_B_LO + swz64(off));
            }
            #pragma unroll
            for (int mi = 0; mi < 4; ++mi)
                #pragma unroll
                for (int ni = 0; ni < 4; ++ni) {
                    const uint32_t* bb = t[ni >> 1];
                    mma_bf16(acc[mi][ni], ah[mi], bb[(ni & 1) * 2], bb[(ni & 1) * 2 + 1]);
                }
        }
    }

    // ---- epilogue ----
    const int qid = lane >> 2;
    const int tc  = (lane & 3) * 2;
    #pragma unroll
    for (int mi = 0; mi < 4; ++mi) {
        #pragma unroll
        for (int half = 0; half < 2; ++half) {
            const int m = bm + wm + mi * 16 + qid + half * 8;
            const float* rrow = (EPI == 3) ? (resid + (size_t)m * N) : nullptr;
            #pragma unroll
            for (int ni = 0; ni < 4; ++ni) {
                const int n = bn + wn + ni * 8 + tc;
                float v0 = acc[mi][ni][half * 2 + 0] + bias[n];
                float v1 = acc[mi][ni][half * 2 + 1] + bias[n + 1];
                if (EPI == 1) {
                    v0 = 1.0f / (1.0f + expf(-v0));
                    v1 = 1.0f / (1.0f + expf(-v1));
                } else if (EPI == 2) {
                    v0 = expf(v0 + bias2[n]);
                    v1 = expf(v1 + bias2[n + 1]);
                } else if (EPI == 3) {
                    v0 += rrow[n];
                    v1 += rrow[n + 1];
                } else if (EPI == 4) {
                    v0 = 0.5f * v0 * (1.0f + erff(v0 * 0.70710678118654752f));
                    v1 = 0.5f * v1 * (1.0f + erff(v1 * 0.70710678118654752f));
                } else if (EPI == 5) {
                    v0 *= 2.0f;
                    v1 *= 2.0f;
                }
                if (OUTSPLIT) {
                    bf16 h0, l0, h1, l1;
                    splitf(v0, h0, l0);
                    splitf(v1, h1, l1);
                    bf16 hp[2] = {h0, h1}, lp[2] = {l0, l1};
                    *(uint32_t*)(Chi + (size_t)m * N + n) = *(uint32_t*)hp;
                    *(uint32_t*)(Clo + (size_t)m * N + n) = *(uint32_t*)lp;
                } else {
                    float2 o; o.x = v0; o.y = v1;
                    *(float2*)(C + (size_t)m * N + n) = o;
                }
            }
        }
    }
}

// ---------------- launch ----------------
extern "C" void kernel_launch(void* const* d_in, const int* in_sizes, int n_in,
                              void* d_out, int out_size)
{
    const float* x     = (const float*)d_in[0];
    const float* gamma = (const float*)d_in[1];
    const float* beta  = (const float*)d_in[2];
    const float* Wq    = (const float*)d_in[3];
    const float* bq    = (const float*)d_in[4];
    const float* Wk    = (const float*)d_in[5];
    const float* bk    = (const float*)d_in[6];
    const float* Wv    = (const float*)d_in[7];
    const float* bv    = (const float*)d_in[8];
    const float* wbias = (const float*)d_in[9];
    const float* Wo    = (const float*)d_in[10];
    const float* bo    = (const float*)d_in[11];
    const float* W1    = (const float*)d_in[12];
    const float* b1    = (const float*)d_in[13];
    const float* W2    = (const float*)d_in[14];
    const float* b2    = (const float*)d_in[15];
    float* out = (float*)d_out;

    float *x1, *qsig, *numer, *vmat, *x2;
    bf16 *x1hi, *x1lo, *x3hi, *x3lo, *yhi, *ylo, *hhi, *hlo;
    bf16 *wqh, *wql, *wkh, *wkl, *wvh, *wvl, *woh, *wol, *w1h, *w1l, *w2h, *w2l;
    cudaGetSymbolAddress((void**)&x1,       g_x1);
    cudaGetSymbolAddress((void**)&x1hi,     g_x1hi);
    cudaGetSymbolAddress((void**)&x1lo,     g_x1lo);
    cudaGetSymbolAddress((void**)&x3hi,     g_x3hi);
    cudaGetSymbolAddress((void**)&x3lo,     g_x3lo);
    cudaGetSymbolAddress((void**)&qsig,     g_qsig);
    cudaGetSymbolAddress((void**)&numer,    g_numer);
    cudaGetSymbolAddress((void**)&vmat,     g_v);
    cudaGetSymbolAddress((void**)&yhi,      g_yhi);
    cudaGetSymbolAddress((void**)&ylo,      g_ylo);
    cudaGetSymbolAddress((void**)&x2,       g_x2);
    cudaGetSymbolAddress((void**)&hhi,      g_hhi);
    cudaGetSymbolAddress((void**)&hlo,      g_hlo);
    cudaGetSymbolAddress((void**)&wqh, g_wq_hi); cudaGetSymbolAddress((void**)&wql, g_wq_lo);
    cudaGetSymbolAddress((void**)&wkh, g_wk_hi); cudaGetSymbolAddress((void**)&wkl, g_wk_lo);
    cudaGetSymbolAddress((void**)&wvh, g_wv_hi); cudaGetSymbolAddress((void**)&wvl, g_wv_lo);
    cudaGetSymbolAddress((void**)&woh, g_wo_hi); cudaGetSymbolAddress((void**)&wol, g_wo_lo);
    cudaGetSymbolAddress((void**)&w1h, g_w1_hi); cudaGetSymbolAddress((void**)&w1l, g_w1_lo);
    cudaGetSymbolAddress((void**)&w2h, g_w2_hi); cudaGetSymbolAddress((void**)&w2l, g_w2_lo);

    cudaFuncSetAttribute(tc_gemm<0, false>, cudaFuncAttributeMaxDynamicSharedMemorySize, SMEM_BYTES);
    cudaFuncSetAttribute(tc_gemm<1, false>, cudaFuncAttributeMaxDynamicSharedMemorySize, SMEM_BYTES);
    cudaFuncSetAttribute(tc_gemm<2, false>, cudaFuncAttributeMaxDynamicSharedMemorySize, SMEM_BYTES);
    cudaFuncSetAttribute(tc_gemm<3, false>, cudaFuncAttributeMaxDynamicSharedMemorySize, SMEM_BYTES);
    cudaFuncSetAttribute(tc_gemm<4, true >, cudaFuncAttributeMaxDynamicSharedMemorySize, SMEM_BYTES);
    cudaFuncSetAttribute(tc_gemm<5, false>, cudaFuncAttributeMaxDynamicSharedMemorySize, SMEM_BYTES);

    // 0) weight transpose + split (cheap)
    {
        dim3 gDH(HDIM / 32, DDIM / 32);
        dim3 gHD(DDIM / 32, HDIM / 32);
        wsplit_kernel<<<gDH, 256>>>(Wq, wqh, wql, DDIM, HDIM);
        wsplit_kernel<<<gDH, 256>>>(Wk, wkh, wkl, DDIM, HDIM);
        wsplit_kernel<<<gDH, 256>>>(Wv, wvh, wvl, DDIM, HDIM);
        wsplit_kernel<<<gHD, 256>>>(Wo, woh, wol, HDIM, DDIM);
        wsplit_kernel<<<gDH, 256>>>(W1, w1h, w1l, DDIM, HDIM);
        wsplit_kernel<<<gHD, 256>>>(W2, w2h, w2l, HDIM, DDIM);
    }

    // 1) x1 = LN(x), + bf16 split
    ln_split_kernel<true><<<MROWS, 128>>>(x, gamma, beta, x1, x1hi, x1lo);

    // 2-4) Q/K/V GEMMs
    dim3 gQ(HDIM / TN, MROWS / TM);
    tc_gemm<1, false><<<gQ, 256, SMEM_BYTES>>>(x1hi, x1lo, wqh, wql, bq, nullptr,
        nullptr, qsig, nullptr, nullptr, MROWS, HDIM, DDIM);
    tc_gemm<2, false><<<gQ, 256, SMEM_BYTES>>>(x1hi, x1lo, wkh, wkl, bk, wbias,
        nullptr, numer, nullptr, nullptr, MROWS, HDIM, DDIM);
    tc_gemm<0, false><<<gQ, 256, SMEM_BYTES>>>(x1hi, x1lo, wvh, wvl, bv, nullptr,
        nullptr, vmat, nullptr, nullptr, MROWS, HDIM, DDIM);

    // 5) fused reduce + Y split
    aft_ysplit_kernel<<<TH / 1024, 256>>>(numer, vmat, qsig, yhi, ylo);

    // 6) x2 = Y @ Wo + bo + x1
    dim3 gO(DDIM / TN, MROWS / TM);
    tc_gemm<3, false><<<gO, 256, SMEM_BYTES>>>(yhi, ylo, woh, wol, bo, nullptr,
        x1, x2, nullptr, nullptr, MROWS, DDIM, HDIM);

    // 7) x3 = LN(x2) -> bf16 only
    ln_split_kernel<false><<<MROWS, 128>>>(x2, gamma, beta, nullptr, x3hi, x3lo);

    // 8) h = gelu(x3 @ W1 + b1) -> split bf16
    tc_gemm<4, true><<<gQ, 256, SMEM_BYTES>>>(x3hi, x3lo, w1h, w1l, b1, nullptr,
        nullptr, nullptr, hhi, hlo, MROWS, HDIM, DDIM);

    // 9) out = 2*(h @ W2 + b2)
    tc_gemm<5, false><<<gO, 256, SMEM_BYTES>>>(hhi, hlo, w2h, w2l, b2, nullptr,
        nullptr, out, nullptr, nullptr, MROWS, DDIM, HDIM);
}